// round 3
// baseline (speedup 1.0000x reference)
#include <cuda_runtime.h>
#include <cuda_bf16.h>
#include <cstdint>

#define NITER   50
#define EPSF    0.1f
#define PCOEF   (1.0f/1.1f)
#define LOGHUGE 69.07755279f   /* log(1e30) */
#define NB      256
#define NN      256
#define KPAD    264            /* padded row length (bf16): 528B stride, conflict-free */
#define DXC     (1.0f/256.0f)
#define DYC     (1.0f/256.0f)
#define PI2F    1.57079632679489662f

struct Smem {
    uint16_t K0[NN * KPAD];   // 135168 B, bf16 kernel matrix K0 = exp(-C/eps)
    float z[NN];              // exp(10*v_j)
    float w[NN];              // exp(10*u_i)
    float u[NN];
    float v[NN];
    float csave[NN];          // last col-pass sums (for col marginal)
    float part[32][NN];       // partial-sum scratch (32 KB)
    float red[8];
};

__device__ __forceinline__ float bflo(unsigned p) { return __uint_as_float(p << 16); }
__device__ __forceinline__ float bfhi(unsigned p) { return __uint_as_float(p & 0xFFFF0000u); }

__device__ __forceinline__ unsigned pack_bf16(float a, float b) {
    __nv_bfloat162 h = __floats2bfloat162_rn(a, b);   // .x = a (low 16), .y = b (high 16)
    return *reinterpret_cast<unsigned*>(&h);
}

__global__ void __launch_bounds__(1024, 1)
wfr_kernel(const float* __restrict__ D, float* __restrict__ out)
{
    extern __shared__ char smraw[];
    Smem* sm = reinterpret_cast<Smem*>(smraw);
    const int b = blockIdx.x;
    const int t = threadIdx.x;
    const float* __restrict__ Db = D + (size_t)b * (NN * NN);

    // ---------------- Prologue: K0 = (cos(min(2D,pi/2)) + 1e-5)^20  (bf16, SMEM) ---------
    {
        const float4* __restrict__ D4 = reinterpret_cast<const float4*>(Db);
        #pragma unroll 4
        for (int k = 0; k < 16; k++) {
            int i4 = t + k * 1024;
            float4 d = D4[i4];
            int e = i4 << 2;
            int i = e >> 8, j = e & (NN - 1);
            float c0 = __cosf(fminf(d.x * 2.0f, PI2F)) + 1e-5f;
            float c1 = __cosf(fminf(d.y * 2.0f, PI2F)) + 1e-5f;
            float c2 = __cosf(fminf(d.z * 2.0f, PI2F)) + 1e-5f;
            float c3 = __cosf(fminf(d.w * 2.0f, PI2F)) + 1e-5f;
            float k0 = exp2f(20.0f * __log2f(c0));
            float k1 = exp2f(20.0f * __log2f(c1));
            float k2 = exp2f(20.0f * __log2f(c2));
            float k3 = exp2f(20.0f * __log2f(c3));
            uint2 pk = make_uint2(pack_bf16(k0, k1), pack_bf16(k2, k3));
            *reinterpret_cast<uint2*>(&sm->K0[i * KPAD + j]) = pk;
        }
        if (t < NN) { sm->u[t] = 0.0f; sm->v[t] = 0.0f; sm->z[t] = 1.0f; }
    }
    __syncthreads();

    const int row  = t & (NN - 1);
    const int q    = t >> 8;        // quarter index 0..3 (row-style passes)
    const int lane = t & 31;
    const int wp   = t >> 5;        // 32 warps
    const int j0   = lane << 3;     // 8 columns per thread in col pass
    const int ib   = wp << 3;       // 8 rows per warp in col pass

    // ---------------- 50 Sinkhorn iterations (eager rescale) ----------------
    #pragma unroll 1
    for (int it = 0; it < NITER; it++) {
        // row pass: r_i = sum_j K0[i][j] * z[j]   (4 threads per row, 64 cols each)
        {
            const uint16_t* __restrict__ kr = sm->K0 + row * KPAD + q * 64;
            const float*    __restrict__ zq = sm->z + q * 64;
            float a0 = 0.f, a1 = 0.f, a2 = 0.f, a3 = 0.f;
            #pragma unroll
            for (int c = 0; c < 8; c++) {
                uint4  k4 = *reinterpret_cast<const uint4*>(kr + c * 8);
                float4 z0 = *reinterpret_cast<const float4*>(zq + c * 8);
                float4 z1 = *reinterpret_cast<const float4*>(zq + c * 8 + 4);
                a0 = fmaf(bflo(k4.x), z0.x, a0);
                a1 = fmaf(bfhi(k4.x), z0.y, a1);
                a2 = fmaf(bflo(k4.y), z0.z, a2);
                a3 = fmaf(bfhi(k4.y), z0.w, a3);
                a0 = fmaf(bflo(k4.z), z1.x, a0);
                a1 = fmaf(bfhi(k4.z), z1.y, a1);
                a2 = fmaf(bflo(k4.w), z1.z, a2);
                a3 = fmaf(bfhi(k4.w), z1.w, a3);
            }
            sm->part[q][row] = (a0 + a1) + (a2 + a3);
        }
        __syncthreads();
        if (t < NN) {
            float r  = sm->part[0][t] + sm->part[1][t] + sm->part[2][t] + sm->part[3][t];
            float la = -PCOEF * (11.0f * sm->u[t] + __logf(DYC * r));
            la = fminf(la, LOGHUGE);                 // clip a at HUGE
            float un = sm->u[t] + EPSF * la;
            sm->u[t] = un;
            sm->w[t] = __expf(10.0f * un);
        }
        __syncthreads();

        // col pass: c_j = sum_i K0[i][j] * w[i]   (warp: 8 rows x 256 cols; thread: 8 cols)
        {
            const uint16_t* __restrict__ kp = sm->K0 + ib * KPAD + j0;
            float c0 = 0.f, c1 = 0.f, c2 = 0.f, c3 = 0.f, c4 = 0.f, c5 = 0.f, c6 = 0.f, c7 = 0.f;
            #pragma unroll
            for (int ii = 0; ii < 8; ii++) {
                uint4 k4 = *reinterpret_cast<const uint4*>(kp + ii * KPAD);
                float wi = sm->w[ib + ii];
                c0 = fmaf(bflo(k4.x), wi, c0);
                c1 = fmaf(bfhi(k4.x), wi, c1);
                c2 = fmaf(bflo(k4.y), wi, c2);
                c3 = fmaf(bfhi(k4.y), wi, c3);
                c4 = fmaf(bflo(k4.z), wi, c4);
                c5 = fmaf(bfhi(k4.z), wi, c5);
                c6 = fmaf(bflo(k4.w), wi, c6);
                c7 = fmaf(bfhi(k4.w), wi, c7);
            }
            float4* pp = reinterpret_cast<float4*>(&sm->part[wp][j0]);
            pp[0] = make_float4(c0, c1, c2, c3);
            pp[1] = make_float4(c4, c5, c6, c7);
        }
        __syncthreads();
        if (t < NN) {
            float c = 0.0f;
            #pragma unroll
            for (int s = 0; s < 32; s++) c += sm->part[s][t];
            sm->csave[t] = c;
            float lb = -PCOEF * (11.0f * sm->v[t] + __logf(DXC * c));
            lb = fminf(lb, LOGHUGE);
            float vn = sm->v[t] + EPSF * lb;
            sm->v[t] = vn;
            sm->z[t] = __expf(10.0f * vn);
        }
        __syncthreads();
    }

    // ---------------- Epilogue: marginals + transport --------------------------------
    {
        const uint16_t* __restrict__ kr = sm->K0 + row * KPAD + q * 64;
        const float*    __restrict__ zq = sm->z + q * 64;
        const float*    __restrict__ dr = Db + row * NN + q * 64;
        float racc = 0.f, tacc = 0.f;
        #pragma unroll 2
        for (int c = 0; c < 8; c++) {
            uint4  k4 = *reinterpret_cast<const uint4*>(kr + c * 8);
            float4 z0 = *reinterpret_cast<const float4*>(zq + c * 8);
            float4 z1 = *reinterpret_cast<const float4*>(zq + c * 8 + 4);
            float4 d0 = *reinterpret_cast<const float4*>(dr + c * 8);
            float4 d1 = *reinterpret_cast<const float4*>(dr + c * 8 + 4);

            float kz, cc, Cv;
            kz = bflo(k4.x) * z0.x; racc += kz;
            cc = __cosf(fminf(d0.x * 2.0f, PI2F)) + 1e-5f; Cv = -2.0f * __logf(cc); tacc = fmaf(kz, Cv, tacc);
            kz = bfhi(k4.x) * z0.y; racc += kz;
            cc = __cosf(fminf(d0.y * 2.0f, PI2F)) + 1e-5f; Cv = -2.0f * __logf(cc); tacc = fmaf(kz, Cv, tacc);
            kz = bflo(k4.y) * z0.z; racc += kz;
            cc = __cosf(fminf(d0.z * 2.0f, PI2F)) + 1e-5f; Cv = -2.0f * __logf(cc); tacc = fmaf(kz, Cv, tacc);
            kz = bfhi(k4.y) * z0.w; racc += kz;
            cc = __cosf(fminf(d0.w * 2.0f, PI2F)) + 1e-5f; Cv = -2.0f * __logf(cc); tacc = fmaf(kz, Cv, tacc);
            kz = bflo(k4.z) * z1.x; racc += kz;
            cc = __cosf(fminf(d1.x * 2.0f, PI2F)) + 1e-5f; Cv = -2.0f * __logf(cc); tacc = fmaf(kz, Cv, tacc);
            kz = bfhi(k4.z) * z1.y; racc += kz;
            cc = __cosf(fminf(d1.y * 2.0f, PI2F)) + 1e-5f; Cv = -2.0f * __logf(cc); tacc = fmaf(kz, Cv, tacc);
            kz = bflo(k4.w) * z1.z; racc += kz;
            cc = __cosf(fminf(d1.z * 2.0f, PI2F)) + 1e-5f; Cv = -2.0f * __logf(cc); tacc = fmaf(kz, Cv, tacc);
            kz = bfhi(k4.w) * z1.w; racc += kz;
            cc = __cosf(fminf(d1.w * 2.0f, PI2F)) + 1e-5f; Cv = -2.0f * __logf(cc); tacc = fmaf(kz, Cv, tacc);
        }
        sm->part[q][row]     = racc;
        sm->part[4 + q][row] = tacc;
    }
    __syncthreads();

    float val = 0.0f;
    if (t < NN) {
        float w_  = sm->w[t];
        float rm  = DYC * w_ * (sm->part[0][t] + sm->part[1][t] + sm->part[2][t] + sm->part[3][t]);
        float klr = rm * __logf(rm + 1e-10f) - rm + 1.0f;
        float tp  = w_ * (sm->part[4][t] + sm->part[5][t] + sm->part[6][t] + sm->part[7][t]) * (DXC * DYC);
        float cm  = DXC * sm->z[t] * sm->csave[t];
        float klc = cm * __logf(cm + 1e-10f) - cm + 1.0f;
        val = klr * DXC + klc * DYC + tp;
    }
    #pragma unroll
    for (int o = 16; o; o >>= 1) val += __shfl_down_sync(0xFFFFFFFFu, val, o);
    if (t < NN && lane == 0) sm->red[wp] = val;
    __syncthreads();
    if (t == 0) {
        float s = 0.0f;
        #pragma unroll
        for (int i = 0; i < 8; i++) s += sm->red[i];
        out[b] = s;
    }
}

extern "C" void kernel_launch(void* const* d_in, const int* in_sizes, int n_in,
                              void* d_out, int out_size)
{
    const float* D = (const float*)d_in[0];
    float* out = (float*)d_out;
    (void)in_sizes; (void)n_in; (void)out_size;
    size_t smem = sizeof(Smem);
    cudaFuncSetAttribute(wfr_kernel, cudaFuncAttributeMaxDynamicSharedMemorySize, (int)smem);
    wfr_kernel<<<NB, 1024, smem>>>(D, out);
}

// round 4
// speedup vs baseline: 1.2292x; 1.2292x over previous
#include <cuda_runtime.h>
#include <cuda_bf16.h>
#include <cstdint>

#define NITER   50
#define EPSF    0.1f
#define PCOEF   (1.0f/1.1f)
#define LOGHUGE 69.07755279f   /* log(1e30) */
#define NB      256
#define NN      256
#define KPAD    264            /* padded row length (bf16): 528B stride, conflict-free */
#define DXC     (1.0f/256.0f)
#define DYC     (1.0f/256.0f)
#define PI2F    1.57079632679489662f

typedef unsigned long long u64;

struct Smem {
    uint16_t K0[NN * KPAD];   // 135168 B, bf16 kernel matrix K0 = exp(-C/eps)
    float z[NN];              // exp(10*v_j)
    float w[NN];              // exp(10*u_i)
    float csave[NN];          // last col-pass sums (for col marginal)
    float part[16][NN];       // partial-sum scratch (16 KB)
    float red[16];
};

__device__ __forceinline__ unsigned pack_bf16(float a, float b) {
    __nv_bfloat162 h = __floats2bfloat162_rn(a, b);
    return *reinterpret_cast<unsigned*>(&h);
}

// packed f32x2 FMA: d += a*b (elementwise on f32 pairs)
__device__ __forceinline__ void ffma2(u64& d, u64 a, u64 b) {
    asm("fma.rn.f32x2 %0, %1, %2, %0;" : "+l"(d) : "l"(a), "l"(b));
}
// bf16x2 (b1,b0) -> f32 pair (lo=b0, hi=b1)
__device__ __forceinline__ u64 unpack_pair(unsigned p) {
    u64 r;
    asm("{\n\t"
        ".reg .b32 lo, hi;\n\t"
        "shl.b32 lo, %1, 16;\n\t"
        "and.b32 hi, %1, 0xFFFF0000;\n\t"
        "mov.b64 %0, {lo, hi};\n\t"
        "}" : "=l"(r) : "r"(p));
    return r;
}
__device__ __forceinline__ u64 dup_pair(float w) {
    u64 r; asm("mov.b64 %0, {%1, %1};" : "=l"(r) : "f"(w)); return r;
}
__device__ __forceinline__ float pair_sum(u64 p) {
    float lo, hi; asm("mov.b64 {%0, %1}, %2;" : "=f"(lo), "=f"(hi) : "l"(p));
    return lo + hi;
}

__global__ void __launch_bounds__(512, 1)
wfr_kernel(const float* __restrict__ D, float* __restrict__ out)
{
    extern __shared__ char smraw[];
    Smem* sm = reinterpret_cast<Smem*>(smraw);
    const int b = blockIdx.x;
    const int t = threadIdx.x;
    const float* __restrict__ Db = D + (size_t)b * (NN * NN);

    // ---------------- Prologue: K0 = (cos(min(2D,pi/2)) + 1e-5)^20  (bf16, SMEM) ---------
    {
        const float4* __restrict__ D4 = reinterpret_cast<const float4*>(Db);
        #pragma unroll 4
        for (int k = 0; k < 32; k++) {
            int i4 = t + k * 512;
            float4 d = D4[i4];
            int e = i4 << 2;
            int i = e >> 8, j = e & (NN - 1);
            float c0 = __cosf(fminf(d.x * 2.0f, PI2F)) + 1e-5f;
            float c1 = __cosf(fminf(d.y * 2.0f, PI2F)) + 1e-5f;
            float c2 = __cosf(fminf(d.z * 2.0f, PI2F)) + 1e-5f;
            float c3 = __cosf(fminf(d.w * 2.0f, PI2F)) + 1e-5f;
            float k0 = exp2f(20.0f * __log2f(c0));
            float k1 = exp2f(20.0f * __log2f(c1));
            float k2 = exp2f(20.0f * __log2f(c2));
            float k3 = exp2f(20.0f * __log2f(c3));
            uint2 pk = make_uint2(pack_bf16(k0, k1), pack_bf16(k2, k3));
            *reinterpret_cast<uint2*>(&sm->K0[i * KPAD + j]) = pk;
        }
        if (t < NN) sm->z[t] = 1.0f;
    }
    __syncthreads();

    const int lane = t & 31;
    const int wp   = t >> 5;          // 16 warps
    // row pass mapping: warp covers 16 rows x both halves
    const int rrow = (wp << 4) + (lane & 15);  // row for row pass
    const int hh   = lane >> 4;                // column half (0/1)
    // col pass mapping
    const int j0   = lane << 3;       // 8 columns per thread
    const int ib   = wp << 4;         // 16 rows per warp

    float u_reg = 0.0f;               // valid for lane<16 (row rrow)
    float v_reg = 0.0f;               // valid for t<256   (col t)

    // ---------------- 50 Sinkhorn iterations (eager rescale) ----------------
    #pragma unroll 1
    for (int it = 0; it < NITER; it++) {
        // row pass: r_i = sum_j K0[i][j] * z[j]  (2 threads/row, same warp, 128 cols each)
        {
            const uint16_t* __restrict__ kr = sm->K0 + rrow * KPAD + hh * 128;
            const float*    __restrict__ zq = sm->z + hh * 128;
            u64 a0 = 0, a1 = 0, a2 = 0, a3 = 0;
            #pragma unroll
            for (int c = 0; c < 16; c++) {
                uint4      k4  = *reinterpret_cast<const uint4*>(kr + c * 8);
                ulonglong2 zp0 = *reinterpret_cast<const ulonglong2*>(zq + c * 8);
                ulonglong2 zp1 = *reinterpret_cast<const ulonglong2*>(zq + c * 8 + 4);
                ffma2(a0, unpack_pair(k4.x), zp0.x);
                ffma2(a1, unpack_pair(k4.y), zp0.y);
                ffma2(a2, unpack_pair(k4.z), zp1.x);
                ffma2(a3, unpack_pair(k4.w), zp1.y);
            }
            float s = (pair_sum(a0) + pair_sum(a1)) + (pair_sum(a2) + pair_sum(a3));
            float r = s + __shfl_xor_sync(0xFFFFFFFFu, s, 16);
            if (lane < 16) {
                float la = -PCOEF * (11.0f * u_reg + __logf(DYC * r));
                la = fminf(la, LOGHUGE);          // clip a at HUGE
                u_reg += EPSF * la;
                sm->w[rrow] = __expf(10.0f * u_reg);
            }
        }
        __syncthreads();

        // col pass: c_j = sum_i K0[i][j] * w[i]  (warp: 16 rows x 256 cols; thread: 8 cols)
        {
            const uint16_t* __restrict__ kp = sm->K0 + ib * KPAD + j0;
            u64 c0 = 0, c1 = 0, c2 = 0, c3 = 0;
            #pragma unroll
            for (int ii = 0; ii < 16; ii++) {
                uint4 k4 = *reinterpret_cast<const uint4*>(kp + ii * KPAD);
                u64 wi2 = dup_pair(sm->w[ib + ii]);
                ffma2(c0, unpack_pair(k4.x), wi2);
                ffma2(c1, unpack_pair(k4.y), wi2);
                ffma2(c2, unpack_pair(k4.z), wi2);
                ffma2(c3, unpack_pair(k4.w), wi2);
            }
            ulonglong2* pp = reinterpret_cast<ulonglong2*>(&sm->part[wp][j0]);
            pp[0] = make_ulonglong2(c0, c1);
            pp[1] = make_ulonglong2(c2, c3);
        }
        __syncthreads();
        if (t < NN) {
            float c = 0.0f;
            #pragma unroll
            for (int s = 0; s < 16; s++) c += sm->part[s][t];
            sm->csave[t] = c;
            float lb = -PCOEF * (11.0f * v_reg + __logf(DXC * c));
            lb = fminf(lb, LOGHUGE);
            v_reg += EPSF * lb;
            sm->z[t] = __expf(10.0f * v_reg);
        }
        __syncthreads();
    }

    // ---------------- Epilogue: marginals + transport --------------------------------
    const int row = t & (NN - 1);
    const int h   = t >> 8;
    {
        const uint16_t* __restrict__ kr = sm->K0 + row * KPAD + h * 128;
        const float*    __restrict__ zh = sm->z + h * 128;
        const float*    __restrict__ dr = Db + row * NN + h * 128;
        float racc = 0.f, tacc = 0.f;
        #pragma unroll 4
        for (int c = 0; c < 16; c++) {
            uint4  k4 = *reinterpret_cast<const uint4*>(kr + c * 8);
            float4 z0 = *reinterpret_cast<const float4*>(zh + c * 8);
            float4 z1 = *reinterpret_cast<const float4*>(zh + c * 8 + 4);
            float4 d0 = *reinterpret_cast<const float4*>(dr + c * 8);
            float4 d1 = *reinterpret_cast<const float4*>(dr + c * 8 + 4);

            float kz, cc, Cv;
            kz = __uint_as_float(k4.x << 16)          * z0.x; racc += kz;
            cc = __cosf(fminf(d0.x * 2.0f, PI2F)) + 1e-5f; Cv = -2.0f * __logf(cc); tacc = fmaf(kz, Cv, tacc);
            kz = __uint_as_float(k4.x & 0xFFFF0000u)  * z0.y; racc += kz;
            cc = __cosf(fminf(d0.y * 2.0f, PI2F)) + 1e-5f; Cv = -2.0f * __logf(cc); tacc = fmaf(kz, Cv, tacc);
            kz = __uint_as_float(k4.y << 16)          * z0.z; racc += kz;
            cc = __cosf(fminf(d0.z * 2.0f, PI2F)) + 1e-5f; Cv = -2.0f * __logf(cc); tacc = fmaf(kz, Cv, tacc);
            kz = __uint_as_float(k4.y & 0xFFFF0000u)  * z0.w; racc += kz;
            cc = __cosf(fminf(d0.w * 2.0f, PI2F)) + 1e-5f; Cv = -2.0f * __logf(cc); tacc = fmaf(kz, Cv, tacc);
            kz = __uint_as_float(k4.z << 16)          * z1.x; racc += kz;
            cc = __cosf(fminf(d1.x * 2.0f, PI2F)) + 1e-5f; Cv = -2.0f * __logf(cc); tacc = fmaf(kz, Cv, tacc);
            kz = __uint_as_float(k4.z & 0xFFFF0000u)  * z1.y; racc += kz;
            cc = __cosf(fminf(d1.y * 2.0f, PI2F)) + 1e-5f; Cv = -2.0f * __logf(cc); tacc = fmaf(kz, Cv, tacc);
            kz = __uint_as_float(k4.w << 16)          * z1.z; racc += kz;
            cc = __cosf(fminf(d1.z * 2.0f, PI2F)) + 1e-5f; Cv = -2.0f * __logf(cc); tacc = fmaf(kz, Cv, tacc);
            kz = __uint_as_float(k4.w & 0xFFFF0000u)  * z1.w; racc += kz;
            cc = __cosf(fminf(d1.w * 2.0f, PI2F)) + 1e-5f; Cv = -2.0f * __logf(cc); tacc = fmaf(kz, Cv, tacc);
        }
        sm->part[h][row]     = racc;
        sm->part[2 + h][row] = tacc;
    }
    __syncthreads();

    float val = 0.0f;
    if (t < NN) {
        float w_  = sm->w[t];
        float rm  = DYC * w_ * (sm->part[0][t] + sm->part[1][t]);
        float klr = rm * __logf(rm + 1e-10f) - rm + 1.0f;
        float tp  = w_ * (sm->part[2][t] + sm->part[3][t]) * (DXC * DYC);
        float cm  = DXC * sm->z[t] * sm->csave[t];
        float klc = cm * __logf(cm + 1e-10f) - cm + 1.0f;
        val = klr * DXC + klc * DYC + tp;
    }
    #pragma unroll
    for (int o = 16; o; o >>= 1) val += __shfl_down_sync(0xFFFFFFFFu, val, o);
    if (t < NN && lane == 0) sm->red[wp] = val;
    __syncthreads();
    if (t == 0) {
        float s = 0.0f;
        #pragma unroll
        for (int i = 0; i < 8; i++) s += sm->red[i];
        out[b] = s;
    }
}

extern "C" void kernel_launch(void* const* d_in, const int* in_sizes, int n_in,
                              void* d_out, int out_size)
{
    const float* D = (const float*)d_in[0];
    float* out = (float*)d_out;
    (void)in_sizes; (void)n_in; (void)out_size;
    size_t smem = sizeof(Smem);
    cudaFuncSetAttribute(wfr_kernel, cudaFuncAttributeMaxDynamicSharedMemorySize, (int)smem);
    wfr_kernel<<<NB, 512, smem>>>(D, out);
}

// round 5
// speedup vs baseline: 1.3522x; 1.1001x over previous
#include <cuda_runtime.h>
#include <cuda_bf16.h>
#include <cstdint>

#define NITER   50
#define EPSF    0.1f
#define PCOEF   (1.0f/1.1f)
#define LOGHUGE 69.07755279f   /* log(1e30) */
#define NB      256
#define NN      256
#define KPAD    264            /* padded row length (bf16): 528B stride -> ldmatrix conflict-free */
#define DXC     (1.0f/256.0f)
#define DYC     (1.0f/256.0f)
#define PI2F    1.57079632679489662f

struct Smem {
    uint16_t K0[NN * KPAD];   // 135168 B, bf16 kernel matrix K0 = exp(-C/eps)
    float z[NN];              // f32 z (epilogue)
    float w[NN];              // f32 w (epilogue)
    float csave[NN];          // last col-pass sums (col marginal)
    uint32_t zb[NN/2];        // bf16x2 z pairs (B-operand)
    uint32_t wb[NN/2];        // bf16x2 w pairs (B-operand)
    float part[4][NN];        // epilogue scratch
    float red[16];
};

__device__ __forceinline__ unsigned pack_bf16(float a, float b) {
    __nv_bfloat162 h = __floats2bfloat162_rn(a, b);
    return *reinterpret_cast<unsigned*>(&h);
}
__device__ __forceinline__ uint16_t to_bf16u(float a) {
    __nv_bfloat16 h = __float2bfloat16(a);
    return *reinterpret_cast<uint16_t*>(&h);
}

__device__ __forceinline__ void ldmx4(uint32_t addr, uint32_t& r0, uint32_t& r1, uint32_t& r2, uint32_t& r3) {
    asm volatile("ldmatrix.sync.aligned.m8n8.x4.shared.b16 {%0,%1,%2,%3}, [%4];"
                 : "=r"(r0), "=r"(r1), "=r"(r2), "=r"(r3) : "r"(addr));
}
__device__ __forceinline__ void ldmx4t(uint32_t addr, uint32_t& r0, uint32_t& r1, uint32_t& r2, uint32_t& r3) {
    asm volatile("ldmatrix.sync.aligned.m8n8.x4.trans.shared.b16 {%0,%1,%2,%3}, [%4];"
                 : "=r"(r0), "=r"(r1), "=r"(r2), "=r"(r3) : "r"(addr));
}
__device__ __forceinline__ void mma_bf16(float& d0, float& d1, float& d2, float& d3,
                                         uint32_t a0, uint32_t a1, uint32_t a2, uint32_t a3,
                                         uint32_t b0, uint32_t b1) {
    asm volatile("mma.sync.aligned.m16n8k16.row.col.f32.bf16.bf16.f32 "
                 "{%0,%1,%2,%3},{%4,%5,%6,%7},{%8,%9},{%0,%1,%2,%3};"
                 : "+f"(d0), "+f"(d1), "+f"(d2), "+f"(d3)
                 : "r"(a0), "r"(a1), "r"(a2), "r"(a3), "r"(b0), "r"(b1));
}

__global__ void __launch_bounds__(512, 1)
wfr_kernel(const float* __restrict__ D, float* __restrict__ out)
{
    extern __shared__ char smraw[];
    Smem* sm = reinterpret_cast<Smem*>(smraw);
    const int b = blockIdx.x;
    const int t = threadIdx.x;
    const float* __restrict__ Db = D + (size_t)b * (NN * NN);

    // ---------------- Prologue: K0 = (cos(min(2D,pi/2)) + 1e-5)^20  (bf16, SMEM) ---------
    {
        const float4* __restrict__ D4 = reinterpret_cast<const float4*>(Db);
        #pragma unroll 4
        for (int k = 0; k < 32; k++) {
            int i4 = t + k * 512;
            float4 d = D4[i4];
            int e = i4 << 2;
            int i = e >> 8, j = e & (NN - 1);
            float c0 = __cosf(fminf(d.x * 2.0f, PI2F)) + 1e-5f;
            float c1 = __cosf(fminf(d.y * 2.0f, PI2F)) + 1e-5f;
            float c2 = __cosf(fminf(d.z * 2.0f, PI2F)) + 1e-5f;
            float c3 = __cosf(fminf(d.w * 2.0f, PI2F)) + 1e-5f;
            float k0 = exp2f(20.0f * __log2f(c0));
            float k1 = exp2f(20.0f * __log2f(c1));
            float k2 = exp2f(20.0f * __log2f(c2));
            float k3 = exp2f(20.0f * __log2f(c3));
            uint2 pk = make_uint2(pack_bf16(k0, k1), pack_bf16(k2, k3));
            *reinterpret_cast<uint2*>(&sm->K0[i * KPAD + j]) = pk;
        }
        if (t < NN)     sm->z[t] = 1.0f;
        if (t < NN / 2) sm->zb[t] = 0x3F803F80u;   // bf16x2 (1.0, 1.0)
    }
    __syncthreads();

    const int lane    = t & 31;
    const int wp      = t >> 5;         // 16 warps
    const int rowbase = wp << 4;        // 16 rows (row pass) / 16 cols (col pass) per warp
    const bool owner  = (lane & 3) == 0;
    const int  oidx   = rowbase + (lane >> 2);   // owner's first row/col

    uint16_t* zb16 = reinterpret_cast<uint16_t*>(sm->zb);
    uint16_t* wb16 = reinterpret_cast<uint16_t*>(sm->wb);

    const uint32_t k0base = (uint32_t)__cvta_generic_to_shared(sm->K0);
    // row pass A addresses: lanes 0-15 -> rows rowbase+(l&15), k-col block (l>>4)*8
    const uint32_t addrRow = k0base + 2u * ((rowbase + (lane & 15)) * KPAD + ((lane >> 4) << 3));
    // col pass A (K0^T) addresses: row = (l&7) + ((l&16)?8:0), col = rowbase + (l&8)
    const uint32_t addrCol = k0base + 2u * (((lane & 7) + ((lane & 16) >> 1)) * KPAD + rowbase + (lane & 8));

    float u0 = 0.0f, u1 = 0.0f;    // potentials for owner rows (consistent across 4-lane group)
    float v0 = 0.0f, v1 = 0.0f;

    // ---------------- 50 Sinkhorn iterations (eager rescale, tensor-core matvecs) --------
    #pragma unroll 1
    for (int it = 0; it < NITER; it++) {
        // ---- row pass: r = K0 z ----
        {
            float d0 = 0.f, d1 = 0.f, d2 = 0.f, d3 = 0.f;
            float e0 = 0.f, e1 = 0.f, e2 = 0.f, e3 = 0.f;
            #pragma unroll
            for (int c = 0; c < 16; c += 2) {
                uint32_t a0, a1, a2, a3;
                ldmx4(addrRow + c * 32, a0, a1, a2, a3);
                uint32_t b0 = sm->zb[c * 8 + (lane & 3)];
                uint32_t b1 = sm->zb[c * 8 + 4 + (lane & 3)];
                mma_bf16(d0, d1, d2, d3, a0, a1, a2, a3, b0, b1);
                ldmx4(addrRow + c * 32 + 32, a0, a1, a2, a3);
                b0 = sm->zb[c * 8 + 8 + (lane & 3)];
                b1 = sm->zb[c * 8 + 12 + (lane & 3)];
                mma_bf16(e0, e1, e2, e3, a0, a1, a2, a3, b0, b1);
            }
            float r0 = d0 + e0;      // row oidx
            float r1 = d2 + e2;      // row oidx+8
            float la0 = fminf(-PCOEF * (11.0f * u0 + __logf(DYC * r0)), LOGHUGE);
            float la1 = fminf(-PCOEF * (11.0f * u1 + __logf(DYC * r1)), LOGHUGE);
            u0 += EPSF * la0;
            u1 += EPSF * la1;
            float w0 = __expf(10.0f * u0);
            float w1 = __expf(10.0f * u1);
            if (owner) {
                sm->w[oidx]     = w0;  wb16[oidx]     = to_bf16u(w0);
                sm->w[oidx + 8] = w1;  wb16[oidx + 8] = to_bf16u(w1);
            }
        }
        __syncthreads();

        // ---- col pass: c = K0^T w ----
        {
            float d0 = 0.f, d1 = 0.f, d2 = 0.f, d3 = 0.f;
            float e0 = 0.f, e1 = 0.f, e2 = 0.f, e3 = 0.f;
            #pragma unroll
            for (int c = 0; c < 16; c += 2) {
                uint32_t a0, a1, a2, a3;
                ldmx4t(addrCol + c * (32 * KPAD), a0, a1, a2, a3);
                uint32_t b0 = sm->wb[c * 8 + (lane & 3)];
                uint32_t b1 = sm->wb[c * 8 + 4 + (lane & 3)];
                mma_bf16(d0, d1, d2, d3, a0, a1, a2, a3, b0, b1);
                ldmx4t(addrCol + c * (32 * KPAD) + 16 * (2 * KPAD), a0, a1, a2, a3);
                b0 = sm->wb[c * 8 + 8 + (lane & 3)];
                b1 = sm->wb[c * 8 + 12 + (lane & 3)];
                mma_bf16(e0, e1, e2, e3, a0, a1, a2, a3, b0, b1);
            }
            float c0 = d0 + e0;      // col oidx
            float c1 = d2 + e2;      // col oidx+8
            float lb0 = fminf(-PCOEF * (11.0f * v0 + __logf(DXC * c0)), LOGHUGE);
            float lb1 = fminf(-PCOEF * (11.0f * v1 + __logf(DXC * c1)), LOGHUGE);
            v0 += EPSF * lb0;
            v1 += EPSF * lb1;
            float z0 = __expf(10.0f * v0);
            float z1 = __expf(10.0f * v1);
            if (owner) {
                sm->csave[oidx]     = c0;
                sm->csave[oidx + 8] = c1;
                sm->z[oidx]     = z0;  zb16[oidx]     = to_bf16u(z0);
                sm->z[oidx + 8] = z1;  zb16[oidx + 8] = to_bf16u(z1);
            }
        }
        __syncthreads();
    }

    // ---------------- Epilogue: marginals + transport --------------------------------
    const int row = t & (NN - 1);
    const int h   = t >> 8;
    {
        const uint16_t* __restrict__ kr = sm->K0 + row * KPAD + h * 128;
        const float*    __restrict__ zh = sm->z + h * 128;
        const float*    __restrict__ dr = Db + row * NN + h * 128;
        float racc = 0.f, tacc = 0.f;
        #pragma unroll 4
        for (int c = 0; c < 16; c++) {
            uint4  k4 = *reinterpret_cast<const uint4*>(kr + c * 8);
            float4 z0 = *reinterpret_cast<const float4*>(zh + c * 8);
            float4 z1 = *reinterpret_cast<const float4*>(zh + c * 8 + 4);
            float4 d0 = *reinterpret_cast<const float4*>(dr + c * 8);
            float4 d1 = *reinterpret_cast<const float4*>(dr + c * 8 + 4);

            float kz, cc, Cv;
            kz = __uint_as_float(k4.x << 16)          * z0.x; racc += kz;
            cc = __cosf(fminf(d0.x * 2.0f, PI2F)) + 1e-5f; Cv = -2.0f * __logf(cc); tacc = fmaf(kz, Cv, tacc);
            kz = __uint_as_float(k4.x & 0xFFFF0000u)  * z0.y; racc += kz;
            cc = __cosf(fminf(d0.y * 2.0f, PI2F)) + 1e-5f; Cv = -2.0f * __logf(cc); tacc = fmaf(kz, Cv, tacc);
            kz = __uint_as_float(k4.y << 16)          * z0.z; racc += kz;
            cc = __cosf(fminf(d0.z * 2.0f, PI2F)) + 1e-5f; Cv = -2.0f * __logf(cc); tacc = fmaf(kz, Cv, tacc);
            kz = __uint_as_float(k4.y & 0xFFFF0000u)  * z0.w; racc += kz;
            cc = __cosf(fminf(d0.w * 2.0f, PI2F)) + 1e-5f; Cv = -2.0f * __logf(cc); tacc = fmaf(kz, Cv, tacc);
            kz = __uint_as_float(k4.z << 16)          * z1.x; racc += kz;
            cc = __cosf(fminf(d1.x * 2.0f, PI2F)) + 1e-5f; Cv = -2.0f * __logf(cc); tacc = fmaf(kz, Cv, tacc);
            kz = __uint_as_float(k4.z & 0xFFFF0000u)  * z1.y; racc += kz;
            cc = __cosf(fminf(d1.y * 2.0f, PI2F)) + 1e-5f; Cv = -2.0f * __logf(cc); tacc = fmaf(kz, Cv, tacc);
            kz = __uint_as_float(k4.w << 16)          * z1.z; racc += kz;
            cc = __cosf(fminf(d1.z * 2.0f, PI2F)) + 1e-5f; Cv = -2.0f * __logf(cc); tacc = fmaf(kz, Cv, tacc);
            kz = __uint_as_float(k4.w & 0xFFFF0000u)  * z1.w; racc += kz;
            cc = __cosf(fminf(d1.w * 2.0f, PI2F)) + 1e-5f; Cv = -2.0f * __logf(cc); tacc = fmaf(kz, Cv, tacc);
        }
        sm->part[h][row]     = racc;
        sm->part[2 + h][row] = tacc;
    }
    __syncthreads();

    float val = 0.0f;
    if (t < NN) {
        float w_  = sm->w[t];
        float rm  = DYC * w_ * (sm->part[0][t] + sm->part[1][t]);
        float klr = rm * __logf(rm + 1e-10f) - rm + 1.0f;
        float tp  = w_ * (sm->part[2][t] + sm->part[3][t]) * (DXC * DYC);
        float cm  = DXC * sm->z[t] * sm->csave[t];
        float klc = cm * __logf(cm + 1e-10f) - cm + 1.0f;
        val = klr * DXC + klc * DYC + tp;
    }
    #pragma unroll
    for (int o = 16; o; o >>= 1) val += __shfl_down_sync(0xFFFFFFFFu, val, o);
    if (t < NN && lane == 0) sm->red[wp] = val;
    __syncthreads();
    if (t == 0) {
        float s = 0.0f;
        #pragma unroll
        for (int i = 0; i < 8; i++) s += sm->red[i];
        out[b] = s;
    }
}

extern "C" void kernel_launch(void* const* d_in, const int* in_sizes, int n_in,
                              void* d_out, int out_size)
{
    const float* D = (const float*)d_in[0];
    float* out = (float*)d_out;
    (void)in_sizes; (void)n_in; (void)out_size;
    size_t smem = sizeof(Smem);
    cudaFuncSetAttribute(wfr_kernel, cudaFuncAttributeMaxDynamicSharedMemorySize, (int)smem);
    wfr_kernel<<<NB, 512, smem>>>(D, out);
}

// round 6
// speedup vs baseline: 1.7718x; 1.3103x over previous
#include <cuda_runtime.h>
#include <cuda_bf16.h>
#include <cstdint>

#define NITER   50
#define EPSF    0.1f
#define PCOEF   (1.0f/1.1f)
#define LOGHUGE 69.07755279f   /* log(1e30) */
#define NB      256
#define NN      256
#define KPAD    264            /* padded row length (bf16): 528B stride -> ldmatrix conflict-free */
#define DXC     (1.0f/256.0f)
#define DYC     (1.0f/256.0f)
#define PI2F    1.57079632679489662f

typedef unsigned long long u64;

struct __align__(16) Smem {
    uint16_t K0[NN * KPAD];   // 135168 B, bf16 kernel matrix K0 = exp(-C/eps)
    float z[NN];              // f32 z (epilogue only)
    float w[NN];              // f32 w (epilogue only)
    float csave[NN];          // final col sums (epilogue only)
    uint16_t zbp[NN];         // packed bf16 z: B-frag order (chunk,q,h,e)
    uint16_t wbp[NN];         // packed bf16 w: same order
    float part[4][NN];        // epilogue scratch
    float red[16];
};

__device__ __forceinline__ unsigned pack_bf16(float a, float b) {
    __nv_bfloat162 h = __floats2bfloat162_rn(a, b);
    return *reinterpret_cast<unsigned*>(&h);
}
__device__ __forceinline__ uint16_t to_bf16u(float a) {
    __nv_bfloat16 h = __float2bfloat16(a);
    return *reinterpret_cast<uint16_t*>(&h);
}
// packed B-frag index for column/row j: (chunk=j>>4, q=(j&7)>>1, h=(j>>3)&1, e=j&1)
__device__ __forceinline__ int pidx(int j) {
    return (j & ~15) | (((j & 7) >> 1) << 2) | (((j >> 3) & 1) << 1) | (j & 1);
}

__device__ __forceinline__ void ldmx4(uint32_t addr, uint32_t& r0, uint32_t& r1, uint32_t& r2, uint32_t& r3) {
    asm volatile("ldmatrix.sync.aligned.m8n8.x4.shared.b16 {%0,%1,%2,%3}, [%4];"
                 : "=r"(r0), "=r"(r1), "=r"(r2), "=r"(r3) : "r"(addr));
}
__device__ __forceinline__ void ldmx4t(uint32_t addr, uint32_t& r0, uint32_t& r1, uint32_t& r2, uint32_t& r3) {
    asm volatile("ldmatrix.sync.aligned.m8n8.x4.trans.shared.b16 {%0,%1,%2,%3}, [%4];"
                 : "=r"(r0), "=r"(r1), "=r"(r2), "=r"(r3) : "r"(addr));
}
__device__ __forceinline__ void mma_bf16(float& d0, float& d1, float& d2, float& d3,
                                         uint32_t a0, uint32_t a1, uint32_t a2, uint32_t a3,
                                         uint32_t b0, uint32_t b1) {
    asm volatile("mma.sync.aligned.m16n8k16.row.col.f32.bf16.bf16.f32 "
                 "{%0,%1,%2,%3},{%4,%5,%6,%7},{%8,%9},{%0,%1,%2,%3};"
                 : "+f"(d0), "+f"(d1), "+f"(d2), "+f"(d3)
                 : "r"(a0), "r"(a1), "r"(a2), "r"(a3), "r"(b0), "r"(b1));
}

__global__ void __launch_bounds__(512, 1)
wfr_kernel(const float* __restrict__ D, float* __restrict__ out)
{
    extern __shared__ char smraw[];
    Smem* sm = reinterpret_cast<Smem*>(smraw);
    const int b = blockIdx.x;
    const int t = threadIdx.x;
    const float* __restrict__ Db = D + (size_t)b * (NN * NN);

    // ---------------- Prologue: K0 = (cos(min(2D,pi/2)) + 1e-5)^20  (bf16, SMEM) ---------
    {
        const float4* __restrict__ D4 = reinterpret_cast<const float4*>(Db);
        #pragma unroll 4
        for (int k = 0; k < 32; k++) {
            int i4 = t + k * 512;
            float4 d = D4[i4];
            int e = i4 << 2;
            int i = e >> 8, j = e & (NN - 1);
            float c0 = __cosf(fminf(d.x * 2.0f, PI2F)) + 1e-5f;
            float c1 = __cosf(fminf(d.y * 2.0f, PI2F)) + 1e-5f;
            float c2 = __cosf(fminf(d.z * 2.0f, PI2F)) + 1e-5f;
            float c3 = __cosf(fminf(d.w * 2.0f, PI2F)) + 1e-5f;
            float k0 = exp2f(20.0f * __log2f(c0));
            float k1 = exp2f(20.0f * __log2f(c1));
            float k2 = exp2f(20.0f * __log2f(c2));
            float k3 = exp2f(20.0f * __log2f(c3));
            uint2 pk = make_uint2(pack_bf16(k0, k1), pack_bf16(k2, k3));
            *reinterpret_cast<uint2*>(&sm->K0[i * KPAD + j]) = pk;
        }
        if (t < NN / 2) reinterpret_cast<uint32_t*>(sm->zbp)[t] = 0x3F803F80u; // z = 1.0
    }
    __syncthreads();

    const int lane    = t & 31;
    const int wp      = t >> 5;         // 16 warps
    const int rowbase = wp << 4;        // 16 rows (row pass) / 16 cols (col pass) per warp
    const bool owner  = (lane & 3) == 0;
    const int  oidx   = rowbase + (lane >> 2);
    const int  q      = lane & 3;

    uint16_t* zb16 = sm->zbp;
    uint16_t* wb16 = sm->wbp;
    const int po0 = pidx(oidx), po1 = pidx(oidx + 8);

    const uint32_t k0base = (uint32_t)__cvta_generic_to_shared(sm->K0);
    const uint32_t addrRow = k0base + 2u * ((rowbase + (lane & 15)) * KPAD + ((lane >> 4) << 3));
    const uint32_t addrCol = k0base + 2u * (((lane & 7) + ((lane & 16) >> 1)) * KPAD + rowbase + (lane & 8));
    const uint32_t zbase = (uint32_t)__cvta_generic_to_shared(sm->zbp) + q * 8;
    const uint32_t wbase = (uint32_t)__cvta_generic_to_shared(sm->wbp) + q * 8;

    // ---- load row-pass A fragments ONCE (K0 is iteration-invariant) ----
    uint32_t A0[16], A1[16], A2[16], A3[16];
    #pragma unroll
    for (int cc = 0; cc < 16; cc++)
        ldmx4(addrRow + cc * 32, A0[cc], A1[cc], A2[cc], A3[cc]);

    float u0 = 0.0f, u1 = 0.0f;
    float v0 = 0.0f, v1 = 0.0f;
    float w0f = 1.0f, w1f = 1.0f, z0f = 1.0f, z1f = 1.0f, c0s = 0.0f, c1s = 0.0f;

    // ---------------- 50 Sinkhorn iterations (eager rescale, tensor-core matvecs) --------
    #pragma unroll 1
    for (int it = 0; it < NITER; it++) {
        // ---- row pass: r = K0 z (A-frags in registers, B via one LDS.64 per chunk) ----
        {
            float d0 = 0.f, d1 = 0.f, d2 = 0.f, d3 = 0.f;
            float e0 = 0.f, e1 = 0.f, e2 = 0.f, e3 = 0.f;
            #pragma unroll
            for (int cc = 0; cc < 16; cc += 2) {
                u64 p0, p1;
                asm volatile("ld.shared.b64 %0, [%1];" : "=l"(p0) : "r"(zbase + cc * 32));
                asm volatile("ld.shared.b64 %0, [%1];" : "=l"(p1) : "r"(zbase + cc * 32 + 32));
                mma_bf16(d0, d1, d2, d3, A0[cc], A1[cc], A2[cc], A3[cc],
                         (uint32_t)p0, (uint32_t)(p0 >> 32));
                mma_bf16(e0, e1, e2, e3, A0[cc + 1], A1[cc + 1], A2[cc + 1], A3[cc + 1],
                         (uint32_t)p1, (uint32_t)(p1 >> 32));
            }
            float r0 = d0 + e0;      // row oidx
            float r1 = d2 + e2;      // row oidx+8
            float la0 = fminf(-PCOEF * (11.0f * u0 + __logf(DYC * r0)), LOGHUGE);
            float la1 = fminf(-PCOEF * (11.0f * u1 + __logf(DYC * r1)), LOGHUGE);
            u0 += EPSF * la0;
            u1 += EPSF * la1;
            w0f = __expf(10.0f * u0);
            w1f = __expf(10.0f * u1);
            if (owner) {
                wb16[po0] = to_bf16u(w0f);
                wb16[po1] = to_bf16u(w1f);
            }
        }
        __syncthreads();

        // ---- col pass: c = K0^T w (streamed transposed ldmatrix) ----
        {
            float d0 = 0.f, d1 = 0.f, d2 = 0.f, d3 = 0.f;
            float e0 = 0.f, e1 = 0.f, e2 = 0.f, e3 = 0.f;
            #pragma unroll
            for (int cc = 0; cc < 16; cc += 2) {
                uint32_t a0, a1, a2, a3;
                u64 p0, p1;
                asm volatile("ld.shared.b64 %0, [%1];" : "=l"(p0) : "r"(wbase + cc * 32));
                asm volatile("ld.shared.b64 %0, [%1];" : "=l"(p1) : "r"(wbase + cc * 32 + 32));
                ldmx4t(addrCol + cc * (16 * 2 * KPAD), a0, a1, a2, a3);
                mma_bf16(d0, d1, d2, d3, a0, a1, a2, a3,
                         (uint32_t)p0, (uint32_t)(p0 >> 32));
                ldmx4t(addrCol + (cc + 1) * (16 * 2 * KPAD), a0, a1, a2, a3);
                mma_bf16(e0, e1, e2, e3, a0, a1, a2, a3,
                         (uint32_t)p1, (uint32_t)(p1 >> 32));
            }
            float c0 = d0 + e0;      // col oidx
            float c1 = d2 + e2;      // col oidx+8
            c0s = c0; c1s = c1;
            float lb0 = fminf(-PCOEF * (11.0f * v0 + __logf(DXC * c0)), LOGHUGE);
            float lb1 = fminf(-PCOEF * (11.0f * v1 + __logf(DXC * c1)), LOGHUGE);
            v0 += EPSF * lb0;
            v1 += EPSF * lb1;
            z0f = __expf(10.0f * v0);
            z1f = __expf(10.0f * v1);
            if (owner) {
                zb16[po0] = to_bf16u(z0f);
                zb16[po1] = to_bf16u(z1f);
            }
        }
        __syncthreads();
    }

    // publish final f32 state for the epilogue
    if (owner) {
        sm->w[oidx]     = w0f;  sm->w[oidx + 8]     = w1f;
        sm->z[oidx]     = z0f;  sm->z[oidx + 8]     = z1f;
        sm->csave[oidx] = c0s;  sm->csave[oidx + 8] = c1s;
    }
    __syncthreads();

    // ---------------- Epilogue: marginals + transport --------------------------------
    const int row = t & (NN - 1);
    const int h   = t >> 8;
    {
        const uint16_t* __restrict__ kr = sm->K0 + row * KPAD + h * 128;
        const float*    __restrict__ zh = sm->z + h * 128;
        const float*    __restrict__ dr = Db + row * NN + h * 128;
        float racc = 0.f, tacc = 0.f;
        #pragma unroll 4
        for (int c = 0; c < 16; c++) {
            uint4  k4 = *reinterpret_cast<const uint4*>(kr + c * 8);
            float4 z0 = *reinterpret_cast<const float4*>(zh + c * 8);
            float4 z1 = *reinterpret_cast<const float4*>(zh + c * 8 + 4);
            float4 d0 = *reinterpret_cast<const float4*>(dr + c * 8);
            float4 d1 = *reinterpret_cast<const float4*>(dr + c * 8 + 4);

            float kz, cc, Cv;
            kz = __uint_as_float(k4.x << 16)          * z0.x; racc += kz;
            cc = __cosf(fminf(d0.x * 2.0f, PI2F)) + 1e-5f; Cv = -2.0f * __logf(cc); tacc = fmaf(kz, Cv, tacc);
            kz = __uint_as_float(k4.x & 0xFFFF0000u)  * z0.y; racc += kz;
            cc = __cosf(fminf(d0.y * 2.0f, PI2F)) + 1e-5f; Cv = -2.0f * __logf(cc); tacc = fmaf(kz, Cv, tacc);
            kz = __uint_as_float(k4.y << 16)          * z0.z; racc += kz;
            cc = __cosf(fminf(d0.z * 2.0f, PI2F)) + 1e-5f; Cv = -2.0f * __logf(cc); tacc = fmaf(kz, Cv, tacc);
            kz = __uint_as_float(k4.y & 0xFFFF0000u)  * z0.w; racc += kz;
            cc = __cosf(fminf(d0.w * 2.0f, PI2F)) + 1e-5f; Cv = -2.0f * __logf(cc); tacc = fmaf(kz, Cv, tacc);
            kz = __uint_as_float(k4.z << 16)          * z1.x; racc += kz;
            cc = __cosf(fminf(d1.x * 2.0f, PI2F)) + 1e-5f; Cv = -2.0f * __logf(cc); tacc = fmaf(kz, Cv, tacc);
            kz = __uint_as_float(k4.z & 0xFFFF0000u)  * z1.y; racc += kz;
            cc = __cosf(fminf(d1.y * 2.0f, PI2F)) + 1e-5f; Cv = -2.0f * __logf(cc); tacc = fmaf(kz, Cv, tacc);
            kz = __uint_as_float(k4.w << 16)          * z1.z; racc += kz;
            cc = __cosf(fminf(d1.z * 2.0f, PI2F)) + 1e-5f; Cv = -2.0f * __logf(cc); tacc = fmaf(kz, Cv, tacc);
            kz = __uint_as_float(k4.w & 0xFFFF0000u)  * z1.w; racc += kz;
            cc = __cosf(fminf(d1.w * 2.0f, PI2F)) + 1e-5f; Cv = -2.0f * __logf(cc); tacc = fmaf(kz, Cv, tacc);
        }
        sm->part[h][row]     = racc;
        sm->part[2 + h][row] = tacc;
    }
    __syncthreads();

    float val = 0.0f;
    if (t < NN) {
        float w_  = sm->w[t];
        float rm  = DYC * w_ * (sm->part[0][t] + sm->part[1][t]);
        float klr = rm * __logf(rm + 1e-10f) - rm + 1.0f;
        float tp  = w_ * (sm->part[2][t] + sm->part[3][t]) * (DXC * DYC);
        float cm  = DXC * sm->z[t] * sm->csave[t];
        float klc = cm * __logf(cm + 1e-10f) - cm + 1.0f;
        val = klr * DXC + klc * DYC + tp;
    }
    #pragma unroll
    for (int o = 16; o; o >>= 1) val += __shfl_down_sync(0xFFFFFFFFu, val, o);
    if (t < NN && lane == 0) sm->red[wp] = val;
    __syncthreads();
    if (t == 0) {
        float s = 0.0f;
        #pragma unroll
        for (int i = 0; i < 8; i++) s += sm->red[i];
        out[b] = s;
    }
}

extern "C" void kernel_launch(void* const* d_in, const int* in_sizes, int n_in,
                              void* d_out, int out_size)
{
    const float* D = (const float*)d_in[0];
    float* out = (float*)d_out;
    (void)in_sizes; (void)n_in; (void)out_size;
    size_t smem = sizeof(Smem);
    cudaFuncSetAttribute(wfr_kernel, cudaFuncAttributeMaxDynamicSharedMemorySize, (int)smem);
    wfr_kernel<<<NB, 512, smem>>>(D, out);
}